// round 16
// baseline (speedup 1.0000x reference)
#include <cuda_runtime.h>
#include <cstdint>

#define BLOCK 256

// ---------------------------------------------------------------------------
// BinaryTreeRNN: out[i] = tree_combine( x[i,0:16] @ W_leaf^T + b_leaf )
// 2-node graph with PDL overlap + warp-local slices (R15 structure), with an
// even/odd-packed matvec (R12 idea) that needs NO dup2 broadcasts:
//   acc_j = ((b_j + sum_m W[j][2m] x[2m]), (sum_m W[j][2m+1] x[2m+1]))
// x pairs come straight out of LDS.128; W stays warp-uniform on the constant
// port because the XOR swizzle read undoes the store XOR (chunk c uniform).
// Setup kernel stores bias as (b_j, 0) so the acc init is one LDC.64.
// ---------------------------------------------------------------------------

struct __align__(16) CParams {
    float  W[8][16];    // natural row-major
    float2 bz[8];       // (b_leaf[j], 0.0f)
    float4 node[7];     // (A, M, C, b): val = A*s + M*l*r + C*sin(s) + b
};

__constant__ CParams cP;

__global__ void setup_kernel(CParams* __restrict__ dst,
                             const float* __restrict__ W,
                             const float* __restrict__ bl,
                             const float* __restrict__ w0,
                             const float* __restrict__ w1,
                             const float* __restrict__ w2,
                             const float* __restrict__ b0,
                             const float* __restrict__ b1,
                             const float* __restrict__ b2,
                             const float* __restrict__ om0,
                             const float* __restrict__ om1,
                             const float* __restrict__ om2)
{
    int t = threadIdx.x;
    if (t < 32) {
        // copy W naturally (vectorized float4)
        reinterpret_cast<float4*>(&dst->W[0][0])[t] =
            reinterpret_cast<const float4*>(W)[t];
    } else if (t < 40) {
        int j = t - 32;
        dst->bz[j] = make_float2(bl[j], 0.0f);
    } else if (t < 47) {
        int i = t - 40;   // 0-3: level2, 4-5: level1, 6: level0
        const float* om;
        float w, b;
        if (i < 4)      { om = om2 + 4 * i;       w = w2[i];     b = b2[i]; }
        else if (i < 6) { om = om1 + 4 * (i - 4); w = w1[i - 4]; b = b1[i - 4]; }
        else            { om = om0;               w = w0[0];     b = b0[0]; }
        float e0 = __expf(om[0]);
        float e1 = __expf(om[1]);
        float e2 = __expf(om[2]);
        float e3 = __expf(om[3]);
        float inv = __fdividef(w, e0 + e1 + e2 + e3);  // fold w into coeffs
        dst->node[i] = make_float4((e0 + e3) * inv, e1 * inv, e2 * inv, b);
    }
    __threadfence();   // push stores to L2 (coherence point for LDC fills)
    __syncthreads();
    asm volatile("griddepcontrol.launch_dependents;" ::: "memory");
}

// ---- packed fp32x2 helpers (sm_103a) --------------------------------------

__device__ __forceinline__ unsigned long long fma2(unsigned long long a,
                                                   unsigned long long b,
                                                   unsigned long long c)
{
    unsigned long long d;
    asm("fma.rn.f32x2 %0, %1, %2, %3;" : "=l"(d) : "l"(a), "l"(b), "l"(c));
    return d;
}

__device__ __forceinline__ void unpack2(unsigned long long v, float& lo, float& hi)
{
    asm("mov.b64 {%0, %1}, %2;" : "=f"(lo), "=f"(hi) : "l"(v));
}

// ---- main kernel -----------------------------------------------------------

__global__ void __launch_bounds__(BLOCK)
tree_rnn_kernel(const float4* __restrict__ x4, float* __restrict__ out, int n)
{
    __shared__ float4 tile[8][128];   // per-warp 2KB slice: 32 rows x 4 f4
    const int t = threadIdx.x;
    const int lane = t & 31;
    const int w = t >> 5;
    float4* ts = tile[w];

    // warp-local coalesced load + XOR-swizzled store (conflict-free)
    const int n4 = n * 4;
    const int base4 = blockIdx.x * (BLOCK * 4) + w * 128;
#pragma unroll
    for (int m = 0; m < 4; m++) {
        int li = m * 32 + lane;           // 0..127 within this warp's tile
        int g4 = base4 + li;
        float4 v;
        if (g4 < n4) v = x4[g4];
        else         v = make_float4(0.f, 0.f, 0.f, 0.f);
        int r = li >> 2;
        int q = li & 3;
        ts[(r << 2) + (q ^ ((r >> 1) & 3))] = v;
    }

    // wait for setup kernel's constant-bank writes (PDL), then warp-sync
    asm volatile("griddepcontrol.wait;" ::: "memory");
    __syncwarp();

    const int row = blockIdx.x * BLOCK + w * 32 + lane;
    if (row >= n) return;

    // even/odd-packed matvec: acc_j = ((even-k partial)+b_j, (odd-k partial))
    // x pairs straight from LDS.128; W chunk index c is warp-uniform (the
    // XOR read undoes the store XOR), so LDC addresses stay uniform.
    const ulonglong2* tb = reinterpret_cast<const ulonglong2*>(ts);
    const int swz = (lane >> 1) & 3;

    unsigned long long acc[8];
#pragma unroll
    for (int j = 0; j < 8; j++)
        acc[j] = *reinterpret_cast<const unsigned long long*>(&cP.bz[j]);

#pragma unroll
    for (int c = 0; c < 4; c++) {
        ulonglong2 xq = tb[(lane << 2) + (c ^ swz)];   // ((x0,x1),(x2,x3)) of chunk c
#pragma unroll
        for (int j = 0; j < 8; j++) {
            ulonglong2 wq =
                *reinterpret_cast<const ulonglong2*>(&cP.W[j][c * 4]);  // LDC.128
            acc[j] = fma2(wq.x, xq.x, acc[j]);
            acc[j] = fma2(wq.y, xq.y, acc[j]);
        }
    }

    float h[8];
#pragma unroll
    for (int j = 0; j < 8; j++) {
        float lo, hi;
        unpack2(acc[j], lo, hi);
        h[j] = lo + hi;
    }

    // tree combine: val = A*s + M*(l*r) + C*sin(s) + b
    float g[4];
#pragma unroll
    for (int k = 0; k < 4; k++) {
        float4 np = cP.node[k];
        float l = h[2 * k], r = h[2 * k + 1];
        float s = l + r;
        g[k] = fmaf(np.x, s, fmaf(np.y, l * r, fmaf(np.z, __sinf(s), np.w)));
    }
    float u[2];
#pragma unroll
    for (int k = 0; k < 2; k++) {
        float4 np = cP.node[4 + k];
        float l = g[2 * k], r = g[2 * k + 1];
        float s = l + r;
        u[k] = fmaf(np.x, s, fmaf(np.y, l * r, fmaf(np.z, __sinf(s), np.w)));
    }
    {
        float4 np = cP.node[6];
        float l = u[0], r = u[1];
        float s = l + r;
        out[row] = fmaf(np.x, s, fmaf(np.y, l * r, fmaf(np.z, __sinf(s), np.w)));
    }
}

extern "C" void kernel_launch(void* const* d_in, const int* in_sizes, int n_in,
                              void* d_out, int out_size)
{
    const float* x      = (const float*)d_in[0];
    const float* W_leaf = (const float*)d_in[1];
    const float* b_leaf = (const float*)d_in[2];
    const float* w0     = (const float*)d_in[3];
    const float* w1     = (const float*)d_in[4];
    const float* w2     = (const float*)d_in[5];
    const float* b0     = (const float*)d_in[6];
    const float* b1     = (const float*)d_in[7];
    const float* b2     = (const float*)d_in[8];
    const float* om0    = (const float*)d_in[9];
    const float* om1    = (const float*)d_in[10];
    const float* om2    = (const float*)d_in[11];

    int n = in_sizes[0] / 16;

    // node 1: fold params and write DIRECTLY into the constant bank
    void* cp_ptr = nullptr;
    cudaGetSymbolAddress(&cp_ptr, cP);
    setup_kernel<<<1, 64>>>((CParams*)cp_ptr, W_leaf, b_leaf,
                            w0, w1, w2, b0, b1, b2, om0, om1, om2);

    // node 2: main kernel with programmatic dependent launch
    int blocks = (n + BLOCK - 1) / BLOCK;

    cudaLaunchConfig_t cfg = {};
    cfg.gridDim  = dim3((unsigned)blocks, 1, 1);
    cfg.blockDim = dim3(BLOCK, 1, 1);
    cfg.dynamicSmemBytes = 0;
    cfg.stream = 0;
    cudaLaunchAttribute attrs[1];
    attrs[0].id = cudaLaunchAttributeProgrammaticStreamSerialization;
    attrs[0].val.programmaticStreamSerializationAllowed = 1;
    cfg.attrs = attrs;
    cfg.numAttrs = 1;

    const float4* x4 = reinterpret_cast<const float4*>(x);
    float* outp = (float*)d_out;
    cudaLaunchKernelEx(&cfg, tree_rnn_kernel, x4, outp, n);
}

// round 17
// speedup vs baseline: 1.0011x; 1.0011x over previous
#include <cuda_runtime.h>
#include <cstdint>

#define BLOCK 256

// ---------------------------------------------------------------------------
// BinaryTreeRNN: out[i] = tree_combine( x[i,0:16] @ W_leaf^T + b_leaf )
// SINGLE kernel node. Block 0 folds all params and writes them directly into
// the __constant__ bank (device-write -> LDC coherence verified in R13), then
// releases a flag. Other blocks overlap their tile LDG/STS with the fold and
// acquire the flag before the first constant-port read. Body == R15 (best
// measured: warp-local swizzled slices, pair-packed fp32x2 matvec, all params
// on the constant port).
// ---------------------------------------------------------------------------

struct __align__(16) CParams {
    float2 Wp[4][16];   // [pair p][k] = (W[2p][k], W[2p+1][k])
    float2 bp[4];       // (b_leaf[2p], b_leaf[2p+1])
    float4 node[7];     // (A, M, C, b): val = A*s + M*l*r + C*sin(s) + b
};

__constant__ CParams cP;
__device__ int gReady;   // zero-init; stays 1 across graph replays (benign:
                         // block 0 rewrites identical param bytes every call)

// ---- packed fp32x2 helpers (sm_103a) --------------------------------------

__device__ __forceinline__ unsigned long long fma2(unsigned long long a,
                                                   unsigned long long b,
                                                   unsigned long long c)
{
    unsigned long long d;
    asm("fma.rn.f32x2 %0, %1, %2, %3;" : "=l"(d) : "l"(a), "l"(b), "l"(c));
    return d;
}

__device__ __forceinline__ unsigned long long dup2(float v)
{
    unsigned long long d;
    asm("mov.b64 %0, {%1, %1};" : "=l"(d) : "f"(v));
    return d;
}

__device__ __forceinline__ void unpack2(unsigned long long v, float& lo, float& hi)
{
    asm("mov.b64 {%0, %1}, %2;" : "=f"(lo), "=f"(hi) : "l"(v));
}

// ---- flag helpers -----------------------------------------------------------

__device__ __forceinline__ int ld_acquire(const int* p)
{
    int v;
    asm volatile("ld.acquire.gpu.global.b32 %0, [%1];"
                 : "=r"(v) : "l"(p) : "memory");
    return v;
}

__device__ __forceinline__ void st_release(int* p, int v)
{
    asm volatile("st.release.gpu.global.b32 [%0], %1;"
                 :: "l"(p), "r"(v) : "memory");
}

// ---- single fused kernel ----------------------------------------------------

__global__ void __launch_bounds__(BLOCK, 8)
tree_rnn_kernel(const float4* __restrict__ x4, float* __restrict__ out, int n,
                CParams* __restrict__ cpw,
                const float* __restrict__ W,
                const float* __restrict__ bl,
                const float* __restrict__ w0,
                const float* __restrict__ w1,
                const float* __restrict__ w2,
                const float* __restrict__ b0,
                const float* __restrict__ b1,
                const float* __restrict__ b2,
                const float* __restrict__ om0,
                const float* __restrict__ om1,
                const float* __restrict__ om2)
{
    __shared__ float4 tile[8][128];   // per-warp 2KB slice: 32 rows x 4 f4
    const int t = threadIdx.x;
    const int lane = t & 31;
    const int w = t >> 5;
    float4* ts = tile[w];

    // ---- block 0: fold params -> constant bank, publish --------------------
    if (blockIdx.x == 0) {
        if (t < 64) {
            int p = t >> 4, k = t & 15;
            cpw->Wp[p][k] = make_float2(W[(2 * p) * 16 + k],
                                        W[(2 * p + 1) * 16 + k]);
        } else if (t < 68) {
            int p = t - 64;
            cpw->bp[p] = make_float2(bl[2 * p], bl[2 * p + 1]);
        } else if (t < 75) {
            int i = t - 68;   // 0-3: level2, 4-5: level1, 6: level0
            const float* om;
            float wv, b;
            if (i < 4)      { om = om2 + 4 * i;       wv = w2[i];     b = b2[i]; }
            else if (i < 6) { om = om1 + 4 * (i - 4); wv = w1[i - 4]; b = b1[i - 4]; }
            else            { om = om0;               wv = w0[0];     b = b0[0]; }
            float e0 = __expf(om[0]);
            float e1 = __expf(om[1]);
            float e2 = __expf(om[2]);
            float e3 = __expf(om[3]);
            float inv = __fdividef(wv, e0 + e1 + e2 + e3);
            cpw->node[i] = make_float4((e0 + e3) * inv, e1 * inv, e2 * inv, b);
        }
        __threadfence();     // params visible in L2 before the flag
        __syncthreads();
        if (t == 0) st_release(&gReady, 1);
    }

    // ---- warp-local coalesced load + XOR-swizzled store (all blocks) -------
    const int n4 = n * 4;
    const int base4 = blockIdx.x * (BLOCK * 4) + w * 128;
#pragma unroll
    for (int m = 0; m < 4; m++) {
        int li = m * 32 + lane;           // 0..127 within this warp's tile
        int g4 = base4 + li;
        float4 v;
        if (g4 < n4) v = x4[g4];
        else         v = make_float4(0.f, 0.f, 0.f, 0.f);
        int r = li >> 2;
        int q = li & 3;
        ts[(r << 2) + (q ^ ((r >> 1) & 3))] = v;
    }

    // ---- acquire the params (hidden under our own in-flight tile loads) ----
    if (blockIdx.x != 0) {
        if (lane == 0) {
            while (!ld_acquire(&gReady)) __nanosleep(64);
        }
    }
    __syncwarp();

    const int row = blockIdx.x * BLOCK + w * 32 + lane;
    if (row >= n) return;

    // gather own row (conflict-free via matching swizzle)
    const int swz = (lane >> 1) & 3;
    float4 v0 = ts[(lane << 2) + (0 ^ swz)];
    float4 v1 = ts[(lane << 2) + (1 ^ swz)];
    float4 v2 = ts[(lane << 2) + (2 ^ swz)];
    float4 v3 = ts[(lane << 2) + (3 ^ swz)];

    unsigned long long xb[16];
    xb[0]  = dup2(v0.x); xb[1]  = dup2(v0.y); xb[2]  = dup2(v0.z); xb[3]  = dup2(v0.w);
    xb[4]  = dup2(v1.x); xb[5]  = dup2(v1.y); xb[6]  = dup2(v1.z); xb[7]  = dup2(v1.w);
    xb[8]  = dup2(v2.x); xb[9]  = dup2(v2.y); xb[10] = dup2(v2.z); xb[11] = dup2(v2.w);
    xb[12] = dup2(v3.x); xb[13] = dup2(v3.y); xb[14] = dup2(v3.z); xb[15] = dup2(v3.w);

    // leaf matvec: weights from the constant port (no L1TEX traffic),
    // bias pre-loaded into the packed accumulator
    float h[8];
#pragma unroll
    for (int p = 0; p < 4; p++) {
        unsigned long long acc =
            *reinterpret_cast<const unsigned long long*>(&cP.bp[p]);
#pragma unroll
        for (int k2 = 0; k2 < 8; k2++) {
            ulonglong2 wq = *reinterpret_cast<const ulonglong2*>(&cP.Wp[p][2 * k2]);
            acc = fma2(wq.x, xb[2 * k2 + 0], acc);
            acc = fma2(wq.y, xb[2 * k2 + 1], acc);
        }
        unpack2(acc, h[2 * p + 0], h[2 * p + 1]);
    }

    // tree combine: val = A*s + M*(l*r) + C*sin(s) + b
    float g[4];
#pragma unroll
    for (int k = 0; k < 4; k++) {
        float4 np = cP.node[k];
        float l = h[2 * k], r = h[2 * k + 1];
        float s = l + r;
        g[k] = fmaf(np.x, s, fmaf(np.y, l * r, fmaf(np.z, __sinf(s), np.w)));
    }
    float u[2];
#pragma unroll
    for (int k = 0; k < 2; k++) {
        float4 np = cP.node[4 + k];
        float l = g[2 * k], r = g[2 * k + 1];
        float s = l + r;
        u[k] = fmaf(np.x, s, fmaf(np.y, l * r, fmaf(np.z, __sinf(s), np.w)));
    }
    {
        float4 np = cP.node[6];
        float l = u[0], r = u[1];
        float s = l + r;
        out[row] = fmaf(np.x, s, fmaf(np.y, l * r, fmaf(np.z, __sinf(s), np.w)));
    }
}

extern "C" void kernel_launch(void* const* d_in, const int* in_sizes, int n_in,
                              void* d_out, int out_size)
{
    const float* x      = (const float*)d_in[0];
    const float* W_leaf = (const float*)d_in[1];
    const float* b_leaf = (const float*)d_in[2];
    const float* w0     = (const float*)d_in[3];
    const float* w1     = (const float*)d_in[4];
    const float* w2     = (const float*)d_in[5];
    const float* b0     = (const float*)d_in[6];
    const float* b1     = (const float*)d_in[7];
    const float* b2     = (const float*)d_in[8];
    const float* om0    = (const float*)d_in[9];
    const float* om1    = (const float*)d_in[10];
    const float* om2    = (const float*)d_in[11];

    int n = in_sizes[0] / 16;

    void* cp_ptr = nullptr;
    cudaGetSymbolAddress(&cp_ptr, cP);

    int blocks = (n + BLOCK - 1) / BLOCK;
    tree_rnn_kernel<<<blocks, BLOCK>>>(
        reinterpret_cast<const float4*>(x), (float*)d_out, n,
        (CParams*)cp_ptr, W_leaf, b_leaf,
        w0, w1, w2, b0, b1, b2, om0, om1, om2);
}